// round 13
// baseline (speedup 1.0000x reference)
#include <cuda_runtime.h>
#include <cuda_fp16.h>
#include <stdint.h>

#define IN_W 256
#define IN_HW 65536
#define OUT_W 254
#define OUT_HW (254 * 254)

// fp16 repacked input: [n][y][part][pos] 16B chunks; part p holds half2 words 4p..4p+3
// word w holds ci pair (lo, lo+1) with lo = ((w>>1)<<1) + ((w&1)<<3)  -> 0,8,2,10,4,12,6,14
__device__ uint4 xh16[32][256][2][256];   // 64 MiB scratch

__global__ void prepass_kernel(const float* __restrict__ x) {
    const int pos = threadIdx.x;
    const int y   = blockIdx.x;
    const int n   = blockIdx.y;
    const float* src = x + (size_t)n * 16 * IN_HW + y * IN_W + pos;
    uint4 out[2];
    uint32_t* ow = (uint32_t*)out;
    #pragma unroll
    for (int wq = 0; wq < 8; wq++) {
        int lo = ((wq >> 1) << 1) + ((wq & 1) << 3);
        __half2 h = __floats2half2_rn(src[(size_t)lo * IN_HW],
                                      src[(size_t)(lo + 1) * IN_HW]);
        ow[wq] = *(uint32_t*)&h;
    }
    xh16[n][y][0][pos] = out[0];
    xh16[n][y][1][pos] = out[1];
}

#define ROWP 528                 // 66 pos * 8 words
#define BUFW (6 * ROWP)          // 3168 words per stage (6 rows, full K)
#define WF_WORDS (9 * 128)       // 9 (ky,kx) tiles of lane-ordered A fragments
#define SMEM_BYTES ((3 * BUFW + WF_WORDS + 16) * 4)   // 42,688 B -> 3 CTAs/SM

__device__ __forceinline__ void mma_f16(float c[4], uint32_t a0, uint32_t a1,
                                        uint32_t a2, uint32_t a3,
                                        uint32_t b0, uint32_t b1) {
    asm("mma.sync.aligned.m16n8k16.row.col.f32.f16.f16.f32 "
        "{%0,%1,%2,%3}, {%4,%5,%6,%7}, {%8,%9}, {%0,%1,%2,%3};"
        : "+f"(c[0]), "+f"(c[1]), "+f"(c[2]), "+f"(c[3])
        : "r"(a0), "r"(a1), "r"(a2), "r"(a3), "r"(b0), "r"(b1));
}
__device__ __forceinline__ float mish_f(float v) {
    if (v > 30.0f) return v;
    float e  = __expf(v);
    float t  = 1.0f + e;
    float t2 = t * t;
    return v * __fdividef(t2 - 1.0f, t2 + 1.0f);
}

__global__ __launch_bounds__(256, 3)
void conv_tc_kernel(const float* __restrict__ w,
                    const float* __restrict__ bias,
                    float* __restrict__ y)
{
    extern __shared__ uint32_t sm[];
    uint32_t* stage = sm;                    // 3 stage buffers [row6][pos66][8 half2-words]
    uint32_t* Wf    = sm + 3 * BUFW;         // lane-ordered fp16 A fragments
    float*    bsm   = (float*)(sm + 3 * BUFW + WF_WORDS);

    const int tid  = threadIdx.x;
    const int wid  = tid >> 5;
    const int lane = tid & 31;
    const int lm   = lane >> 2;
    const int lk   = lane & 3;
    const int X0   = blockIdx.x * 64;
    const int Y0   = blockIdx.y * 16;
    const int n    = blockIdx.z;

    if (tid < 16) bsm[tid] = bias[tid];

    // ---- weight A fragments (m16n8k16): Wf[t*128 + ln*4 + word]
    // word0:(co=lm, ci=2lk,2lk+1) word1:(co+8, same) word2:(co, ci+8 pair) word3:(co+8, ci+8)
    for (int i = tid; i < WF_WORDS; i += 256) {
        int word = i & 3;
        int ln   = (i >> 2) & 31;
        int t    = i >> 7;                   // ky*3+kx, 0..8
        int ky   = t / 3, kx = t % 3;
        int co   = (ln >> 2) + (word & 1) * 8;
        int cilo = 2 * (ln & 3) + (word >> 1) * 8;
        __half2 h = __floats2half2_rn(w[(co * 16 + cilo) * 9 + ky * 3 + kx],
                                      w[(co * 16 + cilo + 1) * 9 + ky * 3 + kx]);
        Wf[i] = *(uint32_t*)&h;
    }

    // ---- loader slots: 768 body chunks = 3/thread, 24 halo (tid<24)
    int srow[3], spart[3], spos[3];
    #pragma unroll
    for (int s = 0; s < 3; s++) {
        int j = tid + 256 * s;
        spart[s] = j & 1;
        int t2 = j >> 1;
        spos[s] = t2 & 63;
        srow[s] = t2 >> 6;                   // 0..5
    }
    int hrow = 0, hpart = 0, hpos = 0;
    if (tid < 24) {
        hpart = tid & 1;
        int t2 = tid >> 1;
        hpos = 64 + (t2 & 1);
        hrow = t2 >> 1;                      // 0..5
    }
    const char* xb = (const char*)xh16;
    const uint32_t sb = (uint32_t)__cvta_generic_to_shared(stage);

    #define LOAD_PH(p, s4)                                                          \
    do {                                                                            \
        int Ys = Y0 + 4 * (s4);                                                     \
        uint32_t sbp = sb + (uint32_t)(p) * (BUFW * 4);                             \
        _Pragma("unroll")                                                           \
        for (int s = 0; s < 3; s++) {                                               \
            int gy = Ys + srow[s]; if (gy > 255) gy = 255;                          \
            int gp = X0 + spos[s]; if (gp > 255) gp = 255;                          \
            const char* src = xb + (size_t)((((n * 256 + gy) * 2 + spart[s]) * 256  \
                                             + gp)) * 16;                           \
            uint32_t dst = sbp + (uint32_t)((srow[s] * ROWP + spos[s] * 8           \
                                             + spart[s] * 4) * 4);                  \
            asm volatile("cp.async.cg.shared.global [%0], [%1], 16;"                \
                         :: "r"(dst), "l"(src));                                    \
        }                                                                           \
        if (tid < 24) {                                                             \
            int gy = Ys + hrow; if (gy > 255) gy = 255;                             \
            int gp = X0 + hpos; if (gp > 255) gp = 255;                             \
            const char* src = xb + (size_t)((((n * 256 + gy) * 2 + hpart) * 256     \
                                             + gp)) * 16;                           \
            uint32_t dst = sbp + (uint32_t)((hrow * ROWP + hpos * 8                 \
                                             + hpart * 4) * 4);                     \
            asm volatile("cp.async.cg.shared.global [%0], [%1], 16;"                \
                         :: "r"(dst), "l"(src));                                    \
        }                                                                           \
        asm volatile("cp.async.commit_group;");                                     \
    } while (0)

    LOAD_PH(0, 0);
    LOAD_PH(1, 1);

    const int rr = wid >> 1;             // warp's row within subtile (0..3)
    const int q  = (wid & 1) * 32;       // warp's 32-pos quarter
    int bi = 0;

    #pragma unroll 1
    for (int s4 = 0; s4 < 4; s4++) {
        if (s4 < 3) asm volatile("cp.async.wait_group 1;");
        else        asm volatile("cp.async.wait_group 0;");
        __syncthreads();

        if (s4 < 2) {
            int li = bi + 2; if (li >= 3) li -= 3;
            LOAD_PH(li, s4 + 2);
        }

        const uint32_t* Ab = stage + bi * BUFW;
        float c[4][4];
        #pragma unroll
        for (int j = 0; j < 4; j++)
            #pragma unroll
            for (int e = 0; e < 4; e++) c[j][e] = 0.f;

        #pragma unroll
        for (int ky = 0; ky < 3; ky++) {
            const uint4* wf = (const uint4*)(Wf + ky * 3 * 128) + lane;
            uint4 A0 = wf[0];
            uint4 A1 = wf[32];
            uint4 A2 = wf[64];
            const uint32_t* bb = Ab + (rr + ky) * ROWP + (q + lm) * 8 + 2 * lk;
            #pragma unroll
            for (int kx = 0; kx < 3; kx++) {
                uint2 b[4];
                #pragma unroll
                for (int j = 0; j < 4; j++)
                    b[j] = *(const uint2*)(bb + kx * 8 + j * 64);
                uint4 Ax = (kx == 0) ? A0 : (kx == 1) ? A1 : A2;
                #pragma unroll
                for (int j = 0; j < 4; j++)
                    mma_f16(c[j], Ax.x, Ax.y, Ax.z, Ax.w, b[j].x, b[j].y);
            }
        }

        const int yo = Y0 + 4 * s4 + rr;
        if (yo < OUT_W) {
            float b0f = bsm[lm] - 0.7f;
            float b1f = bsm[lm + 8] - 0.7f;
            float* y0 = y + ((size_t)n * 16 + lm) * OUT_HW + (size_t)yo * OUT_W;
            float* y1 = y0 + 8 * OUT_HW;
            #pragma unroll
            for (int j = 0; j < 4; j++) {
                int xo = X0 + q + 8 * j + 2 * lk;   // even; float2 pair fully in/out
                if (xo < OUT_W) {
                    float2 v0, v1;
                    v0.x = mish_f(c[j][0] + b0f);
                    v0.y = mish_f(c[j][1] + b0f);
                    v1.x = mish_f(c[j][2] + b1f);
                    v1.y = mish_f(c[j][3] + b1f);
                    *(float2*)(y0 + xo) = v0;
                    *(float2*)(y1 + xo) = v1;
                }
            }
        }

        bi = (bi == 2) ? 0 : bi + 1;
    }
}

extern "C" void kernel_launch(void* const* d_in, const int* in_sizes, int n_in,
                              void* d_out, int out_size)
{
    const float* x  = (const float*)d_in[0];
    const float* w  = (const float*)d_in[1];
    const float* b  = (const float*)d_in[2];
    float* y = (float*)d_out;

    cudaFuncSetAttribute(conv_tc_kernel,
                         cudaFuncAttributeMaxDynamicSharedMemorySize, SMEM_BYTES);

    int N = in_sizes[0] / (16 * IN_HW);                 // 32
    prepass_kernel<<<dim3(256, N), 256>>>(x);
    dim3 grid(4, 16, N);                                // 2048 CTAs
    conv_tc_kernel<<<grid, 256, SMEM_BYTES>>>(w, b, y);
}

// round 15
// speedup vs baseline: 1.0640x; 1.0640x over previous
#include <cuda_runtime.h>
#include <cuda_fp16.h>
#include <stdint.h>

#define IN_W 256
#define IN_HW 65536
#define OUT_W 254
#define OUT_HW (254 * 254)

// fp16 repacked input: [n][y][part][pos] 16B chunks; part p holds half2 words 4p..4p+3
// word w holds ci pair (lo, lo+1) with lo = ((w>>1)<<1) + ((w&1)<<3)  -> 0,8,2,10,4,12,6,14
__device__ uint4 xh16[32][256][2][256];   // 64 MiB scratch

__global__ void prepass_kernel(const float* __restrict__ x) {
    const int pos = threadIdx.x;
    const int y   = blockIdx.x;
    const int n   = blockIdx.y;
    const float* src = x + (size_t)n * 16 * IN_HW + y * IN_W + pos;
    uint4 out[2];
    uint32_t* ow = (uint32_t*)out;
    #pragma unroll
    for (int wq = 0; wq < 8; wq++) {
        int lo = ((wq >> 1) << 1) + ((wq & 1) << 3);
        __half2 h = __floats2half2_rn(src[(size_t)lo * IN_HW],
                                      src[(size_t)(lo + 1) * IN_HW]);
        ow[wq] = *(uint32_t*)&h;
    }
    xh16[n][y][0][pos] = out[0];
    xh16[n][y][1][pos] = out[1];
}

#define ROWP 528                 // 66 pos * 8 half2-words per ring row
#define RING_WORDS (16 * ROWP)   // 16-row rolling ring: 8448 words
#define WF_WORDS (9 * 128)
#define SMEM_BYTES ((RING_WORDS + WF_WORDS + 16) * 4)   // 38,464 B -> 4 CTAs/SM

__device__ __forceinline__ void mma_f16(float c[4], uint32_t a0, uint32_t a1,
                                        uint32_t a2, uint32_t a3,
                                        uint32_t b0, uint32_t b1) {
    asm("mma.sync.aligned.m16n8k16.row.col.f32.f16.f16.f32 "
        "{%0,%1,%2,%3}, {%4,%5,%6,%7}, {%8,%9}, {%0,%1,%2,%3};"
        : "+f"(c[0]), "+f"(c[1]), "+f"(c[2]), "+f"(c[3])
        : "r"(a0), "r"(a1), "r"(a2), "r"(a3), "r"(b0), "r"(b1));
}
__device__ __forceinline__ float mish_f(float v) {
    if (v > 30.0f) return v;
    float e  = __expf(v);
    float t  = 1.0f + e;
    float t2 = t * t;
    return v * __fdividef(t2 - 1.0f, t2 + 1.0f);
}

__global__ __launch_bounds__(256, 4)
void conv_tc_kernel(const float* __restrict__ w,
                    const float* __restrict__ bias,
                    float* __restrict__ y)
{
    extern __shared__ uint32_t sm[];
    uint32_t* ring = sm;                     // 16-row fp16 ring [slot][pos66][8 words]
    uint32_t* Wf   = sm + RING_WORDS;
    float*    bsm  = (float*)(sm + RING_WORDS + WF_WORDS);

    const int tid  = threadIdx.x;
    const int wid  = tid >> 5;
    const int lane = tid & 31;
    const int lm   = lane >> 2;
    const int lk   = lane & 3;
    const int X0   = blockIdx.x * 64;
    const int Y0   = blockIdx.y * 16;
    const int n    = blockIdx.z;

    if (tid < 16) bsm[tid] = bias[tid];

    // ---- weight A fragments (m16n8k16): Wf[t*128 + ln*4 + word]
    for (int i = tid; i < WF_WORDS; i += 256) {
        int word = i & 3;
        int ln   = (i >> 2) & 31;
        int t    = i >> 7;                   // ky*3+kx
        int ky   = t / 3, kx = t % 3;
        int co   = (ln >> 2) + (word & 1) * 8;
        int cilo = 2 * (ln & 3) + (word >> 1) * 8;
        __half2 h = __floats2half2_rn(w[(co * 16 + cilo) * 9 + ky * 3 + kx],
                                      w[(co * 16 + cilo + 1) * 9 + ky * 3 + kx]);
        Wf[i] = *(uint32_t*)&h;
    }

    // ---- loader slots: 4 new rows/phase = 512 body chunks (2/thread) + 16 halo
    int srow[2], spart[2], spos[2];
    #pragma unroll
    for (int s = 0; s < 2; s++) {
        int j = tid + 256 * s;
        spart[s] = j & 1;
        int t2 = j >> 1;
        spos[s] = t2 & 63;                   // 0..63
        srow[s] = t2 >> 6;                   // 0..3
    }
    int hrow = 0, hpart = 0, hpos = 0;
    if (tid < 16) {
        hrow  = tid >> 2;                    // 0..3
        hpos  = 64 + ((tid >> 1) & 1);       // 64,65
        hpart = tid & 1;
    }
    const char* xb = (const char*)xh16;
    const uint32_t sb = (uint32_t)__cvta_generic_to_shared(ring);

    // group g = tile rows 4g..4g+3 -> ring slots (4g+row)&15
    // NOTE: macro local renamed (rbase) — must NOT shadow the caller's loop var.
    #define LOAD_G(g)                                                               \
    do {                                                                            \
        int Ys    = Y0 + 4 * (g);                                                   \
        int rbase = 4 * (g);                                                        \
        _Pragma("unroll")                                                           \
        for (int s = 0; s < 2; s++) {                                               \
            int gy = Ys + srow[s]; if (gy > 255) gy = 255;                          \
            const char* src = xb + (size_t)((((n * 256 + gy) * 2 + spart[s]) * 256  \
                                             + X0 + spos[s])) * 16;                 \
            uint32_t dst = sb + (uint32_t)((((rbase + srow[s]) & 15) * ROWP         \
                                            + spos[s] * 8 + spart[s] * 4) * 4);     \
            asm volatile("cp.async.cg.shared.global [%0], [%1], 16;"                \
                         :: "r"(dst), "l"(src));                                    \
        }                                                                           \
        if (tid < 16) {                                                             \
            int gy = Ys + hrow; if (gy > 255) gy = 255;                             \
            int gp = X0 + hpos; if (gp > 255) gp = 255;                             \
            const char* src = xb + (size_t)((((n * 256 + gy) * 2 + hpart) * 256     \
                                             + gp)) * 16;                           \
            uint32_t dst = sb + (uint32_t)((((rbase + hrow) & 15) * ROWP            \
                                            + hpos * 8 + hpart * 4) * 4);           \
            asm volatile("cp.async.cg.shared.global [%0], [%1], 16;"                \
                         :: "r"(dst), "l"(src));                                    \
        }                                                                           \
        asm volatile("cp.async.commit_group;");                                     \
    } while (0)

    LOAD_G(0);
    LOAD_G(1);

    const int rr = wid >> 1;             // warp's row within subtile (0..3)
    const int q  = (wid & 1) * 32;       // warp's 32-pos quarter

    #pragma unroll 1
    for (int s4 = 0; s4 < 4; s4++) {
        // issue next group first (overwrites slots last read 2 subtiles ago — safe:
        // every warp here has passed the previous phase's barrier)
        if (s4 < 3) {
            LOAD_G(s4 + 2);
            asm volatile("cp.async.wait_group 1;");
        } else {
            asm volatile("cp.async.wait_group 0;");
        }
        __syncthreads();                 // group s4+1 data visible to all

        float c[4][4];
        #pragma unroll
        for (int j = 0; j < 4; j++)
            #pragma unroll
            for (int e = 0; e < 4; e++) c[j][e] = 0.f;

        #pragma unroll
        for (int ky = 0; ky < 3; ky++) {
            const uint4* wf = (const uint4*)(Wf + ky * 3 * 128) + lane;
            uint4 A0 = wf[0];
            uint4 A1 = wf[32];
            uint4 A2 = wf[64];
            int slot = (4 * s4 + rr + ky) & 15;
            const uint32_t* bb = ring + slot * ROWP + (q + lm) * 8 + 2 * lk;
            #pragma unroll
            for (int kx = 0; kx < 3; kx++) {
                uint2 b[4];
                #pragma unroll
                for (int j = 0; j < 4; j++)
                    b[j] = *(const uint2*)(bb + kx * 8 + j * 64);
                uint4 Ax = (kx == 0) ? A0 : (kx == 1) ? A1 : A2;
                #pragma unroll
                for (int j = 0; j < 4; j++)
                    mma_f16(c[j], Ax.x, Ax.y, Ax.z, Ax.w, b[j].x, b[j].y);
            }
        }

        const int yo = Y0 + 4 * s4 + rr;
        if (yo < OUT_W) {
            float b0f = bsm[lm] - 0.7f;
            float b1f = bsm[lm + 8] - 0.7f;
            float* y0 = y + ((size_t)n * 16 + lm) * OUT_HW + (size_t)yo * OUT_W;
            float* y1 = y0 + 8 * OUT_HW;
            #pragma unroll
            for (int j = 0; j < 4; j++) {
                int xo = X0 + q + 8 * j + 2 * lk;   // even; float2 pair fully in/out
                if (xo < OUT_W) {
                    float2 v0, v1;
                    v0.x = mish_f(c[j][0] + b0f);
                    v0.y = mish_f(c[j][1] + b0f);
                    v1.x = mish_f(c[j][2] + b1f);
                    v1.y = mish_f(c[j][3] + b1f);
                    *(float2*)(y0 + xo) = v0;
                    *(float2*)(y1 + xo) = v1;
                }
            }
        }
    }
}

extern "C" void kernel_launch(void* const* d_in, const int* in_sizes, int n_in,
                              void* d_out, int out_size)
{
    const float* x  = (const float*)d_in[0];
    const float* w  = (const float*)d_in[1];
    const float* b  = (const float*)d_in[2];
    float* y = (float*)d_out;

    cudaFuncSetAttribute(conv_tc_kernel,
                         cudaFuncAttributeMaxDynamicSharedMemorySize, SMEM_BYTES);

    int N = in_sizes[0] / (16 * IN_HW);                 // 32
    prepass_kernel<<<dim3(256, N), 256>>>(x);
    dim3 grid(4, 16, N);                                // 2048 CTAs
    conv_tc_kernel<<<grid, 256, SMEM_BYTES>>>(w, b, y);
}

// round 16
// speedup vs baseline: 1.3922x; 1.3084x over previous
#include <cuda_runtime.h>
#include <cuda_fp16.h>
#include <stdint.h>

#define IN_W 256
#define IN_HW 65536
#define OUT_W 254
#define OUT_HW (254 * 254)

#define ROWP 528                 // 66 pos * 8 half2-words per ring row
#define RING_WORDS (16 * ROWP)   // 16-row rolling fp16 ring
#define WF_WORDS (9 * 128)
#define SMEM_BYTES ((RING_WORDS + WF_WORDS + 16) * 4)   // 38,464 B

__device__ __forceinline__ void mma_f16(float c[4], uint32_t a0, uint32_t a1,
                                        uint32_t a2, uint32_t a3,
                                        uint32_t b0, uint32_t b1) {
    asm("mma.sync.aligned.m16n8k16.row.col.f32.f16.f16.f32 "
        "{%0,%1,%2,%3}, {%4,%5,%6,%7}, {%8,%9}, {%0,%1,%2,%3};"
        : "+f"(c[0]), "+f"(c[1]), "+f"(c[2]), "+f"(c[3])
        : "r"(a0), "r"(a1), "r"(a2), "r"(a3), "r"(b0), "r"(b1));
}
__device__ __forceinline__ float mish_f(float v) {
    if (v > 30.0f) return v;
    float e  = __expf(v);
    float t  = 1.0f + e;
    float t2 = t * t;
    return v * __fdividef(t2 - 1.0f, t2 + 1.0f);
}

// load one (row,pos,part) item: 8 fp32 from gmem (ci pairs per word LUT)
#define LDG_ITEM(V, row_, pos_, part_, Ys)                                      \
    do {                                                                        \
        int gy = (Ys) + (row_); if (gy > 255) gy = 255;   /* guarded rows */    \
        int gx = X0 + (pos_);   if (gx > 255) gx = 255;   /* guarded cols */    \
        const float* p_ = xn + gy * IN_W + gx;                                  \
        _Pragma("unroll")                                                       \
        for (int w_ = 0; w_ < 4; w_++) {                                        \
            int wq_ = 4 * (part_) + w_;                                         \
            int lo_ = ((wq_ & 1) << 3) + ((wq_ >> 1) << 1);                     \
            (V)[2 * w_]     = p_[(size_t)lo_ * IN_HW];                          \
            (V)[2 * w_ + 1] = p_[(size_t)(lo_ + 1) * IN_HW];                    \
        }                                                                       \
    } while (0)

// convert + store one item into ring slot (4g+row)&15
#define STS_ITEM(V, row_, pos_, part_, g)                                       \
    do {                                                                        \
        uint4 q_;                                                               \
        uint32_t* qw_ = (uint32_t*)&q_;                                         \
        _Pragma("unroll")                                                       \
        for (int w_ = 0; w_ < 4; w_++) {                                        \
            __half2 h_ = __floats2half2_rn((V)[2 * w_], (V)[2 * w_ + 1]);       \
            qw_[w_] = *(uint32_t*)&h_;                                          \
        }                                                                       \
        *(uint4*)(ring + ((4 * (g) + (row_)) & 15) * ROWP                       \
                  + (pos_) * 8 + (part_) * 4) = q_;                             \
    } while (0)

__global__ __launch_bounds__(256, 3)
void conv_tc_kernel(const float* __restrict__ x,
                    const float* __restrict__ w,
                    const float* __restrict__ bias,
                    float* __restrict__ y)
{
    extern __shared__ uint32_t sm[];
    uint32_t* ring = sm;                     // fp16 ring [slot16][pos66][8 words]
    uint32_t* Wf   = sm + RING_WORDS;
    float*    bsm  = (float*)(sm + RING_WORDS + WF_WORDS);

    const int tid  = threadIdx.x;
    const int wid  = tid >> 5;
    const int lane = tid & 31;
    const int lm   = lane >> 2;
    const int lk   = lane & 3;
    const int X0   = blockIdx.x * 64;
    const int Y0   = blockIdx.y * 16;
    const int n    = blockIdx.z;

    if (tid < 16) bsm[tid] = bias[tid];

    // ---- weight A fragments (m16n8k16): Wf[t*128 + ln*4 + word]
    for (int i = tid; i < WF_WORDS; i += 256) {
        int word = i & 3;
        int ln   = (i >> 2) & 31;
        int t    = i >> 7;                   // ky*3+kx
        int ky   = t / 3, kx = t % 3;
        int co   = (ln >> 2) + (word & 1) * 8;
        int cilo = 2 * (ln & 3) + (word >> 1) * 8;
        __half2 h = __floats2half2_rn(w[(co * 16 + cilo) * 9 + ky * 3 + kx],
                                      w[(co * 16 + cilo + 1) * 9 + ky * 3 + kx]);
        Wf[i] = *(uint32_t*)&h;
    }

    // ---- loader slots: 4 rows/group = 512 body items (2/thread) + 16 halo
    int srow[2], spart[2], spos[2];
    #pragma unroll
    for (int s = 0; s < 2; s++) {
        int j = tid + 256 * s;
        spart[s] = j & 1;
        spos[s]  = (j >> 1) & 63;
        srow[s]  = j >> 7;                   // s=0: rows 0-1, s=1: rows 2-3
    }
    int hrow = 0, hpart = 0, hpos = 0;
    if (tid < 16) {
        hrow  = tid >> 2;
        hpos  = 64 + ((tid >> 1) & 1);
        hpart = tid & 1;
    }
    const float* xn = x + (size_t)n * 16 * IN_HW;

    // ---- prologue: groups 0,1 synchronously
    {
        float V0[8], V1[8], VHp[8];
        #pragma unroll
        for (int g = 0; g < 2; g++) {
            LDG_ITEM(V0, srow[0], spos[0], spart[0], Y0 + 4 * g);
            LDG_ITEM(V1, srow[1], spos[1], spart[1], Y0 + 4 * g);
            if (tid < 16) LDG_ITEM(VHp, hrow, hpos, hpart, Y0 + 4 * g);
            STS_ITEM(V0, srow[0], spos[0], spart[0], g);
            STS_ITEM(V1, srow[1], spos[1], spart[1], g);
            if (tid < 16) STS_ITEM(VHp, hrow, hpos, hpart, g);
        }
    }
    __syncthreads();

    const int rr = wid >> 1;             // warp's row within subtile (0..3)
    const int q  = (wid & 1) * 32;       // warp's 32-pos quarter
    float V[2][8], VH[8];

    #pragma unroll 1
    for (int s4 = 0; s4 < 4; s4++) {
        const int gld  = s4 + 2;
        const int rlim = (gld == 4) ? 2 : 4;   // group 4 = rows 16,17 only

        // prefetch LDGs for group gld — consumed after compute (latency hidden)
        if (s4 < 3) {
            #pragma unroll
            for (int s = 0; s < 2; s++)
                if (srow[s] < rlim)
                    LDG_ITEM(V[s], srow[s], spos[s], spart[s], Y0 + 4 * gld);
            if (tid < 16 && hrow < rlim)
                LDG_ITEM(VH, hrow, hpos, hpart, Y0 + 4 * gld);
        }

        // ---- 36 MMAs on ring groups s4, s4+1
        float c[4][4];
        #pragma unroll
        for (int j = 0; j < 4; j++)
            #pragma unroll
            for (int e = 0; e < 4; e++) c[j][e] = 0.f;

        #pragma unroll
        for (int ky = 0; ky < 3; ky++) {
            const uint4* wf = (const uint4*)(Wf + ky * 3 * 128) + lane;
            uint4 A0 = wf[0];
            uint4 A1 = wf[32];
            uint4 A2 = wf[64];
            int slot = (4 * s4 + rr + ky) & 15;
            const uint32_t* bb = ring + slot * ROWP + (q + lm) * 8 + 2 * lk;
            #pragma unroll
            for (int kx = 0; kx < 3; kx++) {
                uint2 b[4];
                #pragma unroll
                for (int j = 0; j < 4; j++)
                    b[j] = *(const uint2*)(bb + kx * 8 + j * 64);
                uint4 Ax = (kx == 0) ? A0 : (kx == 1) ? A1 : A2;
                #pragma unroll
                for (int j = 0; j < 4; j++)
                    mma_f16(c[j], Ax.x, Ax.y, Ax.z, Ax.w, b[j].x, b[j].y);
            }
        }

        // ---- epilogue
        const int yo = Y0 + 4 * s4 + rr;
        if (yo < OUT_W) {
            float b0f = bsm[lm] - 0.7f;
            float b1f = bsm[lm + 8] - 0.7f;
            float* y0 = y + ((size_t)n * 16 + lm) * OUT_HW + (size_t)yo * OUT_W;
            float* y1 = y0 + 8 * OUT_HW;
            #pragma unroll
            for (int j = 0; j < 4; j++) {
                int xo = X0 + q + 8 * j + 2 * lk;   // even; float2 pair fully in/out
                if (xo < OUT_W) {
                    float2 v0, v1;
                    v0.x = mish_f(c[j][0] + b0f);
                    v0.y = mish_f(c[j][1] + b0f);
                    v1.x = mish_f(c[j][2] + b1f);
                    v1.y = mish_f(c[j][3] + b1f);
                    *(float2*)(y0 + xo) = v0;
                    *(float2*)(y1 + xo) = v1;
                }
            }
        }

        // ---- convert + store group gld (slots disjoint from this phase's reads)
        if (s4 < 3) {
            #pragma unroll
            for (int s = 0; s < 2; s++)
                if (srow[s] < rlim)
                    STS_ITEM(V[s], srow[s], spos[s], spart[s], gld);
            if (tid < 16 && hrow < rlim)
                STS_ITEM(VH, hrow, hpos, hpart, gld);
        }
        __syncthreads();
    }
}

extern "C" void kernel_launch(void* const* d_in, const int* in_sizes, int n_in,
                              void* d_out, int out_size)
{
    const float* x  = (const float*)d_in[0];
    const float* w  = (const float*)d_in[1];
    const float* b  = (const float*)d_in[2];
    float* y = (float*)d_out;

    cudaFuncSetAttribute(conv_tc_kernel,
                         cudaFuncAttributeMaxDynamicSharedMemorySize, SMEM_BYTES);

    int N = in_sizes[0] / (16 * IN_HW);                 // 32
    dim3 grid(4, 16, N);                                // 2048 CTAs
    conv_tc_kernel<<<grid, 256, SMEM_BYTES>>>(x, w, b, y);
}